// round 3
// baseline (speedup 1.0000x reference)
#include <cuda_runtime.h>
#include <math.h>
#include <stdint.h>

#define Sdim 2048
#define Edim 512
#define WIN  11
#define Fdim 5632              // WIN * Edim
#define NTH  512

// ---------------- smem byte offsets ----------------
#define XS_OFF    0                          // float xs[8][5632]  = 180224 B
#define WB0_OFF   180224                     // g0 W ring: 2 bufs x 6 rows x 2048 B = 24576
#define WB1_OFF   (WB0_OFF + 2*6*2048)       // g1 W ring: 2 bufs x 5 rows x 2048 B = 20480
#define GATES_OFF (WB1_OFF + 2*5*2048)       // 225280, 96 floats
#define MB_OFF    (GATES_OFF + 96*4)         // 225664, 15 mbarriers (4 W + 11 xrow)
#define SMEM_BYTES (MB_OFF + 16*8)           // 225792

// ---------------- PTX helpers ----------------
__device__ __forceinline__ uint32_t s2u(const void* p) {
    return (uint32_t)__cvta_generic_to_shared(p);
}
__device__ __forceinline__ void mbar_init(uint32_t a, uint32_t cnt) {
    asm volatile("mbarrier.init.shared.b64 [%0], %1;" :: "r"(a), "r"(cnt) : "memory");
}
__device__ __forceinline__ void mbar_expect_tx(uint32_t a, uint32_t bytes) {
    asm volatile("mbarrier.arrive.expect_tx.shared.b64 _, [%0], %1;"
                 :: "r"(a), "r"(bytes) : "memory");
}
__device__ __forceinline__ void mbar_wait(uint32_t mbar, uint32_t parity) {
    asm volatile(
        "{\n\t.reg .pred P;\n\t"
        "WAIT_%=:\n\t"
        "mbarrier.try_wait.parity.acquire.cta.shared::cta.b64 P, [%0], %1, 0x989680;\n\t"
        "@P bra.uni DONE_%=;\n\t"
        "bra.uni WAIT_%=;\n\t"
        "DONE_%=:\n\t}"
        :: "r"(mbar), "r"(parity) : "memory");
}
__device__ __forceinline__ void bulk_g2s(uint32_t dst, const void* src,
                                         uint32_t bytes, uint32_t mbar) {
    asm volatile(
        "cp.async.bulk.shared::cluster.global.mbarrier::complete_tx::bytes [%0], [%1], %2, [%3];"
        :: "r"(dst), "l"(src), "r"(bytes), "r"(mbar) : "memory");
}
// Packed dual-fp32 FMA: a.{x,y} += {xlo,xhi} * w
__device__ __forceinline__ void ffma2(float2& a, float xlo, float xhi, float w) {
    asm("{\n\t.reg .b64 X, Wd, A;\n\t"
        "mov.b64 X, {%2, %3};\n\t"
        "mov.b64 Wd, {%4, %4};\n\t"
        "mov.b64 A, {%0, %1};\n\t"
        "fma.rn.f32x2 A, X, Wd, A;\n\t"
        "mov.b64 {%0, %1}, A;\n\t}"
        : "+f"(a.x), "+f"(a.y)
        : "f"(xlo), "f"(xhi), "f"(w));
}

// ---------------- producers ----------------
__device__ __forceinline__ void issue_xrow(char* sm, const float* x, int s, int w) {
    if ((unsigned)(s + w - 5) >= (unsigned)Sdim) return;          // OOB row: stays zero
    uint32_t mb = s2u(sm + MB_OFF) + (4 + w) * 8;
    mbar_expect_tx(mb, 8 * Edim * 4);
    uint32_t dst0 = s2u(sm + XS_OFF) + (uint32_t)(w * Edim) * 4;
    const float* src0 = x + (size_t)(s + w - 5) * Edim;
    #pragma unroll
    for (int b = 0; b < 8; b++)
        bulk_g2s(dst0 + (uint32_t)(b * Fdim) * 4,
                 src0 + (size_t)b * Sdim * Edim, Edim * 4, mb);
}
__device__ __forceinline__ void issue_w(char* sm, const float* W, int s, int g, int i) {
    const int rows = g ? 5 : 6;
    const int w0   = g ? 6 : 0;
    uint32_t mb  = s2u(sm + MB_OFF) + (g * 2 + (i & 1)) * 8;
    mbar_expect_tx(mb, rows * Edim * 4);
    const float* src = W + ((size_t)s * WIN + w0) * Fdim + i * Edim;
    uint32_t dst = s2u(sm + (g ? WB1_OFF : WB0_OFF)) + (uint32_t)(i & 1) * rows * 2048;
    for (int r = 0; r < rows; r++)
        bulk_g2s(dst + r * 2048, src + (size_t)r * Fdim, Edim * 4, mb);
}

// ---------------- stage-2 consumer ----------------
template<int ROWS, int G>
__device__ __forceinline__ void stage2_loop(char* sm, const float* x, const float* W,
                                            int s, int h, float2 (&acc)[4][6]) {
    const uint32_t mbb = s2u(sm + MB_OFF);
    const char* wbc = sm + (G ? WB1_OFF : WB0_OFF);
    const float* xs = (const float*)(sm + XS_OFF);

    for (int i = 0; i < WIN; i++) {
        if ((unsigned)(s + i - 5) < (unsigned)Sdim)
            mbar_wait(mbb + (4 + i) * 8, 0);                      // x row i ready
        mbar_wait(mbb + (G * 2 + (i & 1)) * 8, (i >> 1) & 1);     // W chunk i ready

        const float2* wp = (const float2*)(wbc + (size_t)(i & 1) * ROWS * 2048) + h;
        float2 wv[ROWS];
        #pragma unroll
        for (int r = 0; r < ROWS; r++) wv[r] = wp[r * 256];       // row stride 2048 B

        const int f0 = i * Edim + 2 * h;
        float2 xx[8];
        #pragma unroll
        for (int b = 0; b < 8; b++)
            xx[b] = *(const float2*)(xs + (size_t)b * Fdim + f0);

        #pragma unroll
        for (int r = 0; r < ROWS; r++)
            #pragma unroll
            for (int p = 0; p < 4; p++) {
                ffma2(acc[p][r], xx[2*p].x, xx[2*p+1].x, wv[r].x);
                ffma2(acc[p][r], xx[2*p].y, xx[2*p+1].y, wv[r].y);
            }

        asm volatile("bar.sync %0, 256;" :: "r"(G + 1) : "memory"); // buffer drained
        if (h == 0 && i + 2 < WIN) {
            if (G == 0) issue_xrow(sm, x, s, i + 2);
            issue_w(sm, W, s, G, i + 2);
        }
    }
}

// ---------------- kernel ----------------
__global__ __launch_bounds__(NTH, 1)
void winattn_kernel(const float* __restrict__ x,
                    const float* __restrict__ W,
                    const float* __restrict__ bias,
                    float* __restrict__ out) {
    extern __shared__ char sm[];
    const int s   = blockIdx.x;
    const int tid = threadIdx.x;

    if (tid == 0) {
        uint32_t mbb = s2u(sm + MB_OFF);
        #pragma unroll
        for (int k = 0; k < 15; k++) mbar_init(mbb + 8 * k, 1);
    }
    // zero OOB window rows (only 10 of 2048 blocks take this path)
    if (s < 5 || s > Sdim - 6) {
        float4* xs4 = (float4*)(sm + XS_OFF);
        for (int idx = tid; idx < 88 * 128; idx += NTH) {
            int row = idx >> 7;              // 0..87 = b*11 + w
            int w = row - (row / WIN) * WIN;
            if ((unsigned)(s + w - 5) >= (unsigned)Sdim)
                xs4[row * 128 + (idx & 127)] = make_float4(0.f, 0.f, 0.f, 0.f);
        }
    }
    __syncthreads();   // barriers visible + zeros done

    // prologue: 2 chunks in flight per stream
    if (tid == 0) {
        issue_xrow(sm, x, s, 0);
        issue_xrow(sm, x, s, 1);
        issue_w(sm, W, s, 0, 0);
        issue_w(sm, W, s, 0, 1);
    } else if (tid == 256) {
        issue_w(sm, W, s, 1, 0);
        issue_w(sm, W, s, 1, 1);
    }

    const int g = tid >> 8;        // 0: rows w=0..5, 1: rows w=6..10
    const int h = tid & 255;

    float2 acc[4][6];
    #pragma unroll
    for (int p = 0; p < 4; p++)
        #pragma unroll
        for (int r = 0; r < 6; r++)
            acc[p][r] = make_float2(0.f, 0.f);

    if (g == 0) stage2_loop<6, 0>(sm, x, W, s, h, acc);
    else        stage2_loop<5, 1>(sm, x, W, s, h, acc);
    __syncthreads();   // W ring dead from here; alias reduction scratch onto it

    // ---------------- stage 3: reduce -> 88 gates ----------------
    float* af = (float*)acc;
    #pragma unroll
    for (int off = 16; off > 0; off >>= 1) {
        #pragma unroll
        for (int i = 0; i < 48; i++)
            af[i] += __shfl_xor_sync(0xffffffffu, af[i], off);
    }
    float2* red = (float2*)(sm + WB0_OFF);      // [16][24]
    const int lane = tid & 31, wrp = tid >> 5;
    if (lane == 0) {
        #pragma unroll
        for (int p = 0; p < 4; p++)
            #pragma unroll
            for (int r = 0; r < 6; r++)
                red[wrp * 24 + p * 6 + r] = acc[p][r];
    }
    __syncthreads();

    float* gates = (float*)(sm + GATES_OFF);    // gates[b][w], 88 floats
    if (tid < 44) {
        int p = tid / WIN;
        int w = tid - p * WIN;
        int grp  = (w < 6) ? 0 : 1;
        int slot = p * 6 + (grp ? (w - 6) : w);
        float2 t = make_float2(0.f, 0.f);
        #pragma unroll
        for (int q = 0; q < 8; q++) {
            float2 v = red[(grp * 8 + q) * 24 + slot];
            t.x += v.x;
            t.y += v.y;
        }
        float bb = bias[s * WIN + w];
        gates[(2 * p)     * WIN + w] = 1.0f / (1.0f + expf(-(t.x + bb)));
        gates[(2 * p + 1) * WIN + w] = 1.0f / (1.0f + expf(-(t.y + bb)));
    }
    __syncthreads();

    // ---------------- stage 4: score + tanh ----------------
    const int b = tid >> 6;        // 8 groups of 64 threads, one batch each
    const int l = tid & 63;
    float gw[WIN];
    #pragma unroll
    for (int w = 0; w < WIN; w++) gw[w] = gates[b * WIN + w];

    const float* xb = (const float*)(sm + XS_OFF) + (size_t)b * Fdim;
    #pragma unroll
    for (int k = 0; k < 4; k++) {
        int e = 2 * (l + 64 * k);
        float2 a = make_float2(0.f, 0.f);
        #pragma unroll
        for (int w = 0; w < WIN; w++) {
            float2 xv = *(const float2*)(xb + w * Edim + e);
            ffma2(a, xv.x, xv.y, gw[w]);
        }
        float2 o;
        o.x = tanhf(a.x);
        o.y = tanhf(a.y);
        *(float2*)(out + ((size_t)b * Sdim + s) * Edim + e) = o;
    }
}

extern "C" void kernel_launch(void* const* d_in, const int* in_sizes, int n_in,
                              void* d_out, int out_size) {
    const float* x  = (const float*)d_in[0];
    const float* W  = (const float*)d_in[1];
    const float* bv = (const float*)d_in[2];
    float* out = (float*)d_out;

    cudaFuncSetAttribute(winattn_kernel,
                         cudaFuncAttributeMaxDynamicSharedMemorySize, SMEM_BYTES);
    winattn_kernel<<<Sdim, NTH, SMEM_BYTES>>>(x, W, bv, out);
}

// round 4
// speedup vs baseline: 1.2689x; 1.2689x over previous
#include <cuda_runtime.h>
#include <math.h>

#define Sdim 2048
#define Edim 512
#define WIN  11
#define Fdim (WIN * Edim)   // 5632
#define NTH  256

// Packed dual-fp32 FMA: a.{x,y} += {xlo,xhi} * w   (w broadcast to both lanes)
__device__ __forceinline__ void ffma2(float2& a, float xlo, float xhi, float w) {
    asm("{\n\t.reg .b64 X, Wd, A;\n\t"
        "mov.b64 X, {%2, %3};\n\t"
        "mov.b64 Wd, {%4, %4};\n\t"
        "mov.b64 A, {%0, %1};\n\t"
        "fma.rn.f32x2 A, X, Wd, A;\n\t"
        "mov.b64 {%0, %1}, A;\n\t}"
        : "+f"(a.x), "+f"(a.y)
        : "f"(xlo), "f"(xhi), "f"(w));
}

// Packed dual-fp32 FMA, both packed: a.x += xv.x*g.x ; a.y += xv.y*g.y
__device__ __forceinline__ void ffma2v(float2& a, float2 xv, float2 g) {
    asm("{\n\t.reg .b64 X, G, A;\n\t"
        "mov.b64 X, {%2, %3};\n\t"
        "mov.b64 G, {%4, %5};\n\t"
        "mov.b64 A, {%0, %1};\n\t"
        "fma.rn.f32x2 A, X, G, A;\n\t"
        "mov.b64 {%0, %1}, A;\n\t}"
        : "+f"(a.x), "+f"(a.y)
        : "f"(xv.x), "f"(xv.y), "f"(g.x), "f"(g.y));
}

extern __shared__ float smemf[];

// Dynamic smem layout (floats):
//   xs2  : 2 planes * Fdim float2 = 22528 floats (plane p = batches b0+2p, b0+2p+1)
//   red  : 8 warps * 22 float2    = 352 floats
//   gbuf : 22 float2              = 44 floats
// total = 22924 floats = 91696 bytes  -> 2 CTAs/SM

__global__ __launch_bounds__(NTH, 2)
void winattn_kernel(const float* __restrict__ x,
                    const float* __restrict__ W,
                    const float* __restrict__ bias,
                    float* __restrict__ out) {
    const int s    = blockIdx.x >> 1;
    const int half = blockIdx.x & 1;
    const int b0   = half * 4;          // this CTA owns batches b0..b0+3
    const int tid  = threadIdx.x;

    float2* xs2  = (float2*)smemf;                  // [2][Fdim]
    float2* red  = (float2*)(smemf + 2 * Fdim * 2); // [8][22]
    float2* gbuf = red + 8 * 22;                    // [22]

    // ---------------- Stage 1: stage the 4-batch x window into smem --------
    // tasks: (p in 0..1) x (w in 0..10) x (equad in 0..127) = 2816; 11 iters
    #pragma unroll
    for (int k = 0; k < 11; k++) {
        int i   = tid + NTH * k;
        int p   = i / (WIN * 128);
        int rem = i - p * (WIN * 128);
        int w   = rem >> 7;
        int e   = (rem & 127) << 2;
        int row = s + w - 5;
        float4 x0 = make_float4(0.f, 0.f, 0.f, 0.f);
        float4 x1 = make_float4(0.f, 0.f, 0.f, 0.f);
        if ((unsigned)row < (unsigned)Sdim) {
            x0 = *(const float4*)(x + ((size_t)(b0 + 2 * p)     * Sdim + row) * Edim + e);
            x1 = *(const float4*)(x + ((size_t)(b0 + 2 * p + 1) * Sdim + row) * Edim + e);
        }
        float4 A  = make_float4(x0.x, x1.x, x0.y, x1.y);
        float4 Bq = make_float4(x0.z, x1.z, x0.w, x1.w);
        int f = w * Edim + e;                 // multiple of 4
        float4* dst = (float4*)xs2 + p * (Fdim / 2) + (f >> 1);
        dst[0] = A;
        dst[1] = Bq;
    }
    __syncthreads();

    // ---------------- Stage 2: gates GEMV, W streamed via LDG --------------
    float2 acc[2][WIN];
    #pragma unroll
    for (int p = 0; p < 2; p++)
        #pragma unroll
        for (int w = 0; w < WIN; w++)
            acc[p][w] = make_float2(0.f, 0.f);

    const float* Wrow = W + (size_t)s * (WIN * Fdim);

    for (int it = 0; it < 11; it++) {
        int j  = tid + NTH * it;   // float-pair index; f0 = 2*j
        int f0 = 2 * j;

        float2 w2[WIN];
        #pragma unroll
        for (int w = 0; w < WIN; w++)
            w2[w] = *(const float2*)(Wrow + w * Fdim + f0);

        float4 xq[2];
        #pragma unroll
        for (int p = 0; p < 2; p++)
            xq[p] = ((const float4*)xs2)[p * (Fdim / 2) + j];

        #pragma unroll
        for (int w = 0; w < WIN; w++) {
            #pragma unroll
            for (int p = 0; p < 2; p++) {
                ffma2(acc[p][w], xq[p].x, xq[p].y, w2[w].x);
                ffma2(acc[p][w], xq[p].z, xq[p].w, w2[w].y);
            }
        }
    }

    // ---------------- Stage 3: reduce 256 partials -> 44 gates -------------
    float* af = (float*)acc;            // 44 floats
    #pragma unroll
    for (int off = 16; off > 0; off >>= 1) {
        #pragma unroll
        for (int i = 0; i < 44; i++)
            af[i] += __shfl_xor_sync(0xffffffffu, af[i], off);
    }
    const int lane = tid & 31, wrp = tid >> 5;
    if (lane == 0) {
        #pragma unroll
        for (int p = 0; p < 2; p++)
            #pragma unroll
            for (int w = 0; w < WIN; w++)
                red[wrp * 22 + p * WIN + w] = acc[p][w];
    }
    __syncthreads();

    if (tid < 22) {
        float2 t = make_float2(0.f, 0.f);
        #pragma unroll
        for (int q = 0; q < 8; q++) {
            float2 v = red[q * 22 + tid];
            t.x += v.x;
            t.y += v.y;
        }
        int w = tid % WIN;
        float bb = bias[s * WIN + w];
        float2 g;
        g.x = 1.0f / (1.0f + expf(-(t.x + bb)));
        g.y = 1.0f / (1.0f + expf(-(t.y + bb)));
        gbuf[tid] = g;                  // tid == p*WIN + w
    }
    __syncthreads();

    // ---------------- Stage 4: score + tanh ---------------------------------
    const int p = tid >> 7;             // batch-pair within this CTA (0..1)
    const int l = tid & 127;
    float2 gw[WIN];
    #pragma unroll
    for (int w = 0; w < WIN; w++)
        gw[w] = gbuf[p * WIN + w];

    #pragma unroll
    for (int k = 0; k < 4; k++) {
        int e = l + 128 * k;
        float2 a = make_float2(0.f, 0.f);
        #pragma unroll
        for (int w = 0; w < WIN; w++) {
            float2 xv = xs2[p * Fdim + w * Edim + e];
            ffma2v(a, xv, gw[w]);
        }
        out[(size_t)(b0 + 2 * p)     * Sdim * Edim + (size_t)s * Edim + e] = tanhf(a.x);
        out[(size_t)(b0 + 2 * p + 1) * Sdim * Edim + (size_t)s * Edim + e] = tanhf(a.y);
    }
}

extern "C" void kernel_launch(void* const* d_in, const int* in_sizes, int n_in,
                              void* d_out, int out_size) {
    const float* x  = (const float*)d_in[0];
    const float* W  = (const float*)d_in[1];
    const float* bv = (const float*)d_in[2];
    float* out = (float*)d_out;

    const int smem_bytes = (2 * Fdim * 2 + 8 * 22 * 2 + 22 * 2) * (int)sizeof(float); // 91696
    cudaFuncSetAttribute(winattn_kernel,
                         cudaFuncAttributeMaxDynamicSharedMemorySize, smem_bytes);

    winattn_kernel<<<2 * Sdim, NTH, smem_bytes>>>(x, W, bv, out);
}